// round 1
// baseline (speedup 1.0000x reference)
#include <cuda_runtime.h>
#include <cuda_bf16.h>
#include <math.h>

// ---------------------------------------------------------------------------
// GATv2 layer:  fs = x@W_src+b_src, fd = x@W_dst+b_dst   [N,H,D]
//   logit[e,h] = attn[h,:] . leaky_relu(fs[src[e],h,:] + fd[dst[e],h,:])
//   alpha = edge-softmax over dst;  rst[v] = sum alpha * fs[src]
//   out = elu(LayerNorm(rst + out_bias))
// ---------------------------------------------------------------------------

#define N_NODES 50000
#define E_EDGES 800000
#define F_DIM   128         // IN_F == OUT_F == H*D
#define NEG_SLOPE 0.2f
#define LN_EPS  1e-12f

// ---- device scratch (no allocations allowed) ----
__device__ float g_fs[(size_t)N_NODES * F_DIM];   // src projections
__device__ float g_fd[(size_t)N_NODES * F_DIM];   // dst projections
__device__ int   g_deg[N_NODES];
__device__ int   g_rowptr[N_NODES + 1];
__device__ int   g_cursor[N_NODES];
__device__ int   g_src_sorted[E_EDGES];           // src node id per CSR slot

// ---------------------------------------------------------------------------
// 0) zero degree counters
// ---------------------------------------------------------------------------
__global__ void zero_kernel() {
    int i = blockIdx.x * blockDim.x + threadIdx.x;
    if (i < N_NODES) g_deg[i] = 0;
}

// ---------------------------------------------------------------------------
// 1) GEMM: out[b] = x @ W + bias ; blockIdx.y selects (W_src->g_fs) / (W_dst->g_fd)
//    BM=64, BN=128, BK=16, 256 threads, 8x4 microtile.
// ---------------------------------------------------------------------------
#define BM 64
#define BN 128
#define BK 16

__global__ __launch_bounds__(256) void gemm_kernel(
    const float* __restrict__ x,
    const float* __restrict__ Wsrc, const float* __restrict__ bsrc,
    const float* __restrict__ Wdst, const float* __restrict__ bdst)
{
    const float* W    = (blockIdx.y == 0) ? Wsrc : Wdst;
    const float* bias = (blockIdx.y == 0) ? bsrc : bdst;
    float* out        = (blockIdx.y == 0) ? g_fs : g_fd;

    __shared__ float As[BK][BM];
    __shared__ float Bs[BK][BN];

    const int tid  = threadIdx.x;
    const int row0 = blockIdx.x * BM;
    const int ty   = tid >> 5;        // 0..7  -> 8 rows each
    const int tx   = tid & 31;        // 0..31 -> 4 cols each

    float acc[8][4];
#pragma unroll
    for (int i = 0; i < 8; i++)
#pragma unroll
        for (int j = 0; j < 4; j++) acc[i][j] = 0.f;

    for (int kt = 0; kt < F_DIM; kt += BK) {
        // load A tile 64x16 (transposed into As[k][row]); float4 per thread
        {
            int arow = tid >> 2;            // 0..63
            int ak   = (tid & 3) * 4;       // 0,4,8,12
            int grow = row0 + arow;
            float4 av = make_float4(0.f, 0.f, 0.f, 0.f);
            if (grow < N_NODES)
                av = *(const float4*)(x + (size_t)grow * F_DIM + kt + ak);
            As[ak + 0][arow] = av.x;
            As[ak + 1][arow] = av.y;
            As[ak + 2][arow] = av.z;
            As[ak + 3][arow] = av.w;
        }
        // load B tile 16x128; 2 float4 per thread
        {
            int br = tid >> 5;              // 0..7
            int bc = (tid & 31) * 4;        // 0..124
#pragma unroll
            for (int rr = 0; rr < 2; rr++) {
                float4 bv = *(const float4*)(W + (size_t)(kt + br + rr * 8) * F_DIM + bc);
                *(float4*)&Bs[br + rr * 8][bc] = bv;
            }
        }
        __syncthreads();

#pragma unroll
        for (int kk = 0; kk < BK; kk++) {
            float a[8], b[4];
#pragma unroll
            for (int i = 0; i < 8; i++) a[i] = As[kk][ty * 8 + i];
            float4 bv = *(const float4*)&Bs[kk][tx * 4];
            b[0] = bv.x; b[1] = bv.y; b[2] = bv.z; b[3] = bv.w;
#pragma unroll
            for (int i = 0; i < 8; i++)
#pragma unroll
                for (int j = 0; j < 4; j++)
                    acc[i][j] = fmaf(a[i], b[j], acc[i][j]);
        }
        __syncthreads();
    }

    // epilogue
    const int c = tx * 4;
    float4 bv = *(const float4*)(bias + c);
#pragma unroll
    for (int i = 0; i < 8; i++) {
        int r = row0 + ty * 8 + i;
        if (r < N_NODES) {
            float4 v;
            v.x = acc[i][0] + bv.x;
            v.y = acc[i][1] + bv.y;
            v.z = acc[i][2] + bv.z;
            v.w = acc[i][3] + bv.w;
            *(float4*)(out + (size_t)r * F_DIM + c) = v;
        }
    }
}

// ---------------------------------------------------------------------------
// 2) degree histogram over dst
// ---------------------------------------------------------------------------
__global__ void hist_kernel(const int* __restrict__ dst) {
    int e = blockIdx.x * blockDim.x + threadIdx.x;
    if (e < E_EDGES) atomicAdd(&g_deg[dst[e]], 1);
}

// ---------------------------------------------------------------------------
// 3) exclusive scan of degrees (single block, 1024 threads)
// ---------------------------------------------------------------------------
__global__ __launch_bounds__(1024) void scan_kernel() {
    __shared__ int warpsums[32];
    const int tid  = threadIdx.x;
    const int lane = tid & 31;
    const int wid  = tid >> 5;
    int carry = 0;

    for (int base = 0; base < N_NODES; base += 1024) {
        int i = base + tid;
        int v = (i < N_NODES) ? g_deg[i] : 0;
        int xv = v;
#pragma unroll
        for (int d = 1; d < 32; d <<= 1) {
            int t = __shfl_up_sync(0xffffffffu, xv, d);
            if (lane >= d) xv += t;
        }
        if (lane == 31) warpsums[wid] = xv;
        __syncthreads();
        if (wid == 0) {
            int y = warpsums[lane];
#pragma unroll
            for (int d = 1; d < 32; d <<= 1) {
                int t = __shfl_up_sync(0xffffffffu, y, d);
                if (lane >= d) y += t;
            }
            warpsums[lane] = y;
        }
        __syncthreads();
        int offset = (wid > 0) ? warpsums[wid - 1] : 0;
        int incl = xv + offset;
        int excl = incl - v + carry;
        if (i < N_NODES) { g_rowptr[i] = excl; g_cursor[i] = excl; }
        int total = warpsums[31];
        __syncthreads();
        carry += total;
    }
    if (tid == 0) g_rowptr[N_NODES] = carry;
}

// ---------------------------------------------------------------------------
// 4) scatter src ids into CSR order
// ---------------------------------------------------------------------------
__global__ void scatter_kernel(const int* __restrict__ src, const int* __restrict__ dst) {
    int e = blockIdx.x * blockDim.x + threadIdx.x;
    if (e < E_EDGES) {
        int pos = atomicAdd(&g_cursor[dst[e]], 1);
        g_src_sorted[pos] = src[e];
    }
}

// ---------------------------------------------------------------------------
// 5) fused per-node kernel: one warp per dst node.
//    online softmax over incoming edges + aggregation + LayerNorm + ELU
//    lane l owns features [4l, 4l+4) ; head = l >> 3 (D=32 -> 8 lanes/head)
// ---------------------------------------------------------------------------
__global__ __launch_bounds__(256) void node_kernel(
    const float* __restrict__ attn,
    const float* __restrict__ out_bias,
    const float* __restrict__ ln_w,
    const float* __restrict__ ln_b,
    float* __restrict__ out)
{
    const int gwarp = (blockIdx.x * blockDim.x + threadIdx.x) >> 5;
    const int lane  = threadIdx.x & 31;
    if (gwarp >= N_NODES) return;
    const int v = gwarp;
    const int f = lane * 4;

    const float4 at  = *(const float4*)(attn + f);
    const float4 fdv = *(const float4*)(g_fd + (size_t)v * F_DIM + f);

    const int beg = g_rowptr[v];
    const int end = g_rowptr[v + 1];

    float4 acc = make_float4(0.f, 0.f, 0.f, 0.f);
    float  m = -INFINITY, denom = 0.f;

    for (int p = beg; p < end; p++) {
        int u = g_src_sorted[p];
        float4 fsv = *(const float4*)(g_fs + (size_t)u * F_DIM + f);
        float sx = fsv.x + fdv.x;
        float sy = fsv.y + fdv.y;
        float sz = fsv.z + fdv.z;
        float sw = fsv.w + fdv.w;
        sx = (sx > 0.f) ? sx : NEG_SLOPE * sx;
        sy = (sy > 0.f) ? sy : NEG_SLOPE * sy;
        sz = (sz > 0.f) ? sz : NEG_SLOPE * sz;
        sw = (sw > 0.f) ? sw : NEG_SLOPE * sw;
        float part = sx * at.x + sy * at.y + sz * at.z + sw * at.w;
        // reduce within 8-lane head group
        part += __shfl_xor_sync(0xffffffffu, part, 1);
        part += __shfl_xor_sync(0xffffffffu, part, 2);
        part += __shfl_xor_sync(0xffffffffu, part, 4);
        float logit = part;

        float mn = fmaxf(m, logit);
        float c  = __expf(m - mn);       // 0 on first iter (m = -inf)
        float w  = __expf(logit - mn);
        denom = denom * c + w;
        acc.x = acc.x * c + w * fsv.x;
        acc.y = acc.y * c + w * fsv.y;
        acc.z = acc.z * c + w * fsv.z;
        acc.w = acc.w * c + w * fsv.w;
        m = mn;
    }

    float inv = (end > beg) ? (1.f / denom) : 0.f;
    float4 ob = *(const float4*)(out_bias + f);
    float4 h;
    h.x = acc.x * inv + ob.x;
    h.y = acc.y * inv + ob.y;
    h.z = acc.z * inv + ob.z;
    h.w = acc.w * inv + ob.w;

    // LayerNorm across the warp's 128 features
    float s1 = h.x + h.y + h.z + h.w;
#pragma unroll
    for (int d = 16; d >= 1; d >>= 1) s1 += __shfl_xor_sync(0xffffffffu, s1, d);
    float mean = s1 * (1.f / 128.f);

    float dx = h.x - mean, dy = h.y - mean, dz = h.z - mean, dw = h.w - mean;
    float s2 = dx * dx + dy * dy + dz * dz + dw * dw;
#pragma unroll
    for (int d = 16; d >= 1; d >>= 1) s2 += __shfl_xor_sync(0xffffffffu, s2, d);
    float rstd = rsqrtf(s2 * (1.f / 128.f) + LN_EPS);

    float4 w4 = *(const float4*)(ln_w + f);
    float4 b4 = *(const float4*)(ln_b + f);
    float4 o;
    o.x = dx * rstd * w4.x + b4.x;
    o.y = dy * rstd * w4.y + b4.y;
    o.z = dz * rstd * w4.z + b4.z;
    o.w = dw * rstd * w4.w + b4.w;
    // ELU (alpha = 1)
    o.x = (o.x > 0.f) ? o.x : expm1f(o.x);
    o.y = (o.y > 0.f) ? o.y : expm1f(o.y);
    o.z = (o.z > 0.f) ? o.z : expm1f(o.z);
    o.w = (o.w > 0.f) ? o.w : expm1f(o.w);

    *(float4*)(out + (size_t)v * F_DIM + f) = o;
}

// ---------------------------------------------------------------------------
// launch
// ---------------------------------------------------------------------------
extern "C" void kernel_launch(void* const* d_in, const int* in_sizes, int n_in,
                              void* d_out, int out_size)
{
    const float* x        = (const float*)d_in[0];
    const float* W_src    = (const float*)d_in[1];
    const float* b_src    = (const float*)d_in[2];
    const float* W_dst    = (const float*)d_in[3];
    const float* b_dst    = (const float*)d_in[4];
    const float* attn     = (const float*)d_in[5];
    const float* out_bias = (const float*)d_in[6];
    const float* ln_w     = (const float*)d_in[7];
    const float* ln_b     = (const float*)d_in[8];
    const int*   src      = (const int*)d_in[9];
    const int*   dst      = (const int*)d_in[10];
    float* out = (float*)d_out;

    zero_kernel<<<(N_NODES + 255) / 256, 256>>>();

    dim3 ggrid((N_NODES + BM - 1) / BM, 2);
    gemm_kernel<<<ggrid, 256>>>(x, W_src, b_src, W_dst, b_dst);

    hist_kernel<<<(E_EDGES + 255) / 256, 256>>>(dst);
    scan_kernel<<<1, 1024>>>();
    scatter_kernel<<<(E_EDGES + 255) / 256, 256>>>(src, dst);

    int nwarps  = N_NODES;
    int nblocks = (nwarps * 32 + 255) / 256;
    node_kernel<<<nblocks, 256>>>(attn, out_bias, ln_w, ln_b, out);
}

// round 3
// speedup vs baseline: 1.1073x; 1.1073x over previous
#include <cuda_runtime.h>
#include <cuda_bf16.h>
#include <math.h>
#include <stdint.h>

// ---------------------------------------------------------------------------
// GATv2 layer. GEMMs via mma.sync bf16 (3-term hi/lo split, fp32 accum).
// ---------------------------------------------------------------------------

#define N_NODES 50000
#define E_EDGES 800000
#define F_DIM   128
#define NEG_SLOPE 0.2f
#define LN_EPS  1e-12f

// ---- device scratch ----
__device__ float g_fs[(size_t)N_NODES * F_DIM];
__device__ float g_fd[(size_t)N_NODES * F_DIM];
__device__ int   g_deg[N_NODES];
__device__ int   g_rowptr[N_NODES + 1];
__device__ int   g_cursor[N_NODES];
__device__ int   g_src_sorted[E_EDGES];
__device__ int   g_blocksums[64];
__device__ int   g_blockoff[64];
// W^T hi/lo bf16 images, row-major [n][k]  ([2] = src/dst)
__device__ __nv_bfloat16 g_wt_hi[2][128 * 128];
__device__ __nv_bfloat16 g_wt_lo[2][128 * 128];

__device__ __forceinline__ uint32_t smem_u32(const void* p) {
    uint32_t a;
    asm("{ .reg .u64 t; cvta.to.shared.u64 t, %1; cvt.u32.u64 %0, t; }"
        : "=r"(a) : "l"(p));
    return a;
}
__device__ __forceinline__ uint32_t pack2(float a, float b) {
    __nv_bfloat162 t = __floats2bfloat162_rn(a, b);
    return *reinterpret_cast<uint32_t*>(&t);
}
__device__ __forceinline__ void ldsm_x4(uint32_t* r, uint32_t addr) {
    asm volatile("ldmatrix.sync.aligned.m8n8.x4.shared.b16 {%0,%1,%2,%3}, [%4];"
                 : "=r"(r[0]), "=r"(r[1]), "=r"(r[2]), "=r"(r[3]) : "r"(addr));
}
__device__ __forceinline__ void mma_bf16(float* d, const uint32_t* a,
                                         uint32_t b0, uint32_t b1) {
    asm volatile(
        "mma.sync.aligned.m16n8k16.row.col.f32.bf16.bf16.f32 "
        "{%0,%1,%2,%3}, {%4,%5,%6,%7}, {%8,%9}, {%0,%1,%2,%3};"
        : "+f"(d[0]), "+f"(d[1]), "+f"(d[2]), "+f"(d[3])
        : "r"(a[0]), "r"(a[1]), "r"(a[2]), "r"(a[3]), "r"(b0), "r"(b1));
}

// ---------------------------------------------------------------------------
// W transpose + hi/lo split:  g_wt[n][k] = split(W[k][n])
// ---------------------------------------------------------------------------
__global__ void convert_w_kernel(const float* __restrict__ Wsrc,
                                 const float* __restrict__ Wdst) {
    const int b = blockIdx.x;
    const float* W = b == 0 ? Wsrc : Wdst;
    for (int idx = threadIdx.x; idx < 128 * 128; idx += blockDim.x) {
        int k = idx >> 7, n = idx & 127;
        float v = W[idx];
        __nv_bfloat16 hi = __float2bfloat16(v);
        float r = v - __bfloat162float(hi);
        g_wt_hi[b][n * 128 + k] = hi;
        g_wt_lo[b][n * 128 + k] = __float2bfloat16(r);
    }
}

// ---------------------------------------------------------------------------
// GEMM: CTA = 128-row x-tile; computes BOTH fs and fd (shared A).
// smem (bf16, padded stride 136): A_hi, A_lo, B[2][hi/lo]
// warps 4x2: warp = 32 rows x 64 cols; mma m16n8k16; 3 terms.
// ---------------------------------------------------------------------------
#define PAD 136
#define TILE_B (128 * PAD)            // elements per image
#define SM_TOTAL (6 * TILE_B * 2)     // 208896 bytes

__global__ __launch_bounds__(256, 1) void gemm_mma_kernel(
    const float* __restrict__ x,
    const float* __restrict__ bsrc, const float* __restrict__ bdst)
{
    extern __shared__ __nv_bfloat16 sm[];
    __nv_bfloat16* As_hi = sm;
    __nv_bfloat16* As_lo = sm + TILE_B;
    __nv_bfloat16* Bs[2][2];          // [wsel][0=hi,1=lo]
    Bs[0][0] = sm + 2 * TILE_B;
    Bs[0][1] = sm + 3 * TILE_B;
    Bs[1][0] = sm + 4 * TILE_B;
    Bs[1][1] = sm + 5 * TILE_B;

    const int tid = threadIdx.x, wid = tid >> 5, lane = tid & 31;
    const int wm = wid >> 1, wn = wid & 1;
    const int row0 = blockIdx.x * 128;

    // ---- fill B images (copy, add padding) ----
    for (int i = tid; i < 2048; i += 256) {
        int n = i >> 4, k = (i & 15) << 3;
        *(float4*)(Bs[0][0] + n * PAD + k) = *(const float4*)(g_wt_hi[0] + n * 128 + k);
        *(float4*)(Bs[0][1] + n * PAD + k) = *(const float4*)(g_wt_lo[0] + n * 128 + k);
        *(float4*)(Bs[1][0] + n * PAD + k) = *(const float4*)(g_wt_hi[1] + n * 128 + k);
        *(float4*)(Bs[1][1] + n * PAD + k) = *(const float4*)(g_wt_lo[1] + n * 128 + k);
    }
    // ---- load x tile, split hi/lo ----
    for (int i = tid; i < 4096; i += 256) {
        int r = i >> 5, c = (i & 31) << 2;
        float4 v = make_float4(0.f, 0.f, 0.f, 0.f);
        if (row0 + r < N_NODES)
            v = *(const float4*)(x + (size_t)(row0 + r) * F_DIM + c);
        __nv_bfloat162 h01 = __floats2bfloat162_rn(v.x, v.y);
        __nv_bfloat162 h23 = __floats2bfloat162_rn(v.z, v.w);
        uint32_t lo01 = pack2(v.x - __bfloat162float(h01.x), v.y - __bfloat162float(h01.y));
        uint32_t lo23 = pack2(v.z - __bfloat162float(h23.x), v.w - __bfloat162float(h23.y));
        uint32_t* ph = (uint32_t*)(As_hi + r * PAD + c);
        uint32_t* pl = (uint32_t*)(As_lo + r * PAD + c);
        ph[0] = *reinterpret_cast<uint32_t*>(&h01);
        ph[1] = *reinterpret_cast<uint32_t*>(&h23);
        pl[0] = lo01;
        pl[1] = lo23;
    }
    __syncthreads();

    const uint32_t sbase = smem_u32(sm);
    const int g = lane >> 3, l7 = lane & 7;

    for (int wsel = 0; wsel < 2; wsel++) {
        float acc[2][8][4];
#pragma unroll
        for (int i = 0; i < 2; i++)
#pragma unroll
            for (int j = 0; j < 8; j++)
#pragma unroll
                for (int q = 0; q < 4; q++) acc[i][j][q] = 0.f;

#pragma unroll
        for (int term = 0; term < 3; term++) {
            const __nv_bfloat16* Asm = (term == 2) ? As_lo : As_hi;
            const __nv_bfloat16* Bsm = Bs[wsel][(term == 1) ? 1 : 0];
            const uint32_t abase = sbase + (uint32_t)((Asm - sm) * 2);
            const uint32_t bbase = sbase + (uint32_t)((Bsm - sm) * 2);
#pragma unroll
            for (int k0 = 0; k0 < 128; k0 += 16) {
                uint32_t afr[2][4];
#pragma unroll
                for (int mt = 0; mt < 2; mt++) {
                    int r = wm * 32 + mt * 16 + ((g & 1) << 3) + l7;
                    int c = k0 + ((g >> 1) << 3);
                    ldsm_x4(afr[mt], abase + (uint32_t)(r * PAD + c) * 2);
                }
#pragma unroll
                for (int p = 0; p < 4; p++) {
                    int r = wn * 64 + p * 16 + ((g >> 1) << 3) + l7;
                    int c = k0 + ((g & 1) << 3);
                    uint32_t bfr[4];
                    ldsm_x4(bfr, bbase + (uint32_t)(r * PAD + c) * 2);
#pragma unroll
                    for (int mt = 0; mt < 2; mt++) {
                        mma_bf16(acc[mt][2 * p],     afr[mt], bfr[0], bfr[1]);
                        mma_bf16(acc[mt][2 * p + 1], afr[mt], bfr[2], bfr[3]);
                    }
                }
            }
        }

        // ---- epilogue: bias + store ----
        const float* bias = wsel ? bdst : bsrc;
        float* outp = wsel ? g_fd : g_fs;
#pragma unroll
        for (int mt = 0; mt < 2; mt++) {
#pragma unroll
            for (int nt = 0; nt < 8; nt++) {
                int col = wn * 64 + nt * 8 + (lane & 3) * 2;
                float bx = bias[col], by = bias[col + 1];
                int r0 = row0 + wm * 32 + mt * 16 + (lane >> 2);
                if (r0 < N_NODES) {
                    float2 o = make_float2(acc[mt][nt][0] + bx, acc[mt][nt][1] + by);
                    *(float2*)(outp + (size_t)r0 * F_DIM + col) = o;
                }
                int r1 = r0 + 8;
                if (r1 < N_NODES) {
                    float2 o = make_float2(acc[mt][nt][2] + bx, acc[mt][nt][3] + by);
                    *(float2*)(outp + (size_t)r1 * F_DIM + col) = o;
                }
            }
        }
    }
}

// ---------------------------------------------------------------------------
// histogram / hierarchical scan / scatter
// ---------------------------------------------------------------------------
__global__ void zero_kernel() {
    int i = blockIdx.x * blockDim.x + threadIdx.x;
    if (i < N_NODES) g_deg[i] = 0;
}

__global__ void hist_kernel(const int* __restrict__ dst) {
    int e = blockIdx.x * blockDim.x + threadIdx.x;
    if (e < E_EDGES) atomicAdd(&g_deg[dst[e]], 1);
}

__global__ __launch_bounds__(1024) void scan1_kernel() {
    __shared__ int ws[32];
    const int tid = threadIdx.x, lane = tid & 31, wid = tid >> 5;
    int i = blockIdx.x * 1024 + tid;
    int v = (i < N_NODES) ? g_deg[i] : 0;
    int xv = v;
#pragma unroll
    for (int d = 1; d < 32; d <<= 1) {
        int t = __shfl_up_sync(0xffffffffu, xv, d);
        if (lane >= d) xv += t;
    }
    if (lane == 31) ws[wid] = xv;
    __syncthreads();
    if (wid == 0) {
        int y = ws[lane];
#pragma unroll
        for (int d = 1; d < 32; d <<= 1) {
            int t = __shfl_up_sync(0xffffffffu, y, d);
            if (lane >= d) y += t;
        }
        ws[lane] = y;
    }
    __syncthreads();
    int off = (wid > 0) ? ws[wid - 1] : 0;
    int incl = xv + off;
    if (i < N_NODES) g_rowptr[i] = incl - v;
    if (tid == 1023) g_blocksums[blockIdx.x] = incl;
}

__global__ void scan2_kernel() {
    __shared__ int s[64];
    int t = threadIdx.x;
    int v = (t < 49) ? g_blocksums[t] : 0;
    s[t] = v;
    __syncthreads();
    for (int d = 1; d < 64; d <<= 1) {
        int add = (t >= d) ? s[t - d] : 0;
        __syncthreads();
        s[t] += add;
        __syncthreads();
    }
    g_blockoff[t] = s[t] - v;
}

__global__ __launch_bounds__(1024) void scan3_kernel() {
    int i = blockIdx.x * 1024 + threadIdx.x;
    if (i < N_NODES) {
        int val = g_rowptr[i] + g_blockoff[blockIdx.x];
        g_rowptr[i] = val;
        g_cursor[i] = val;
    }
    if (i == 0) g_rowptr[N_NODES] = E_EDGES;
}

__global__ void scatter_kernel(const int* __restrict__ src, const int* __restrict__ dst) {
    int e = blockIdx.x * blockDim.x + threadIdx.x;
    if (e < E_EDGES) {
        int pos = atomicAdd(&g_cursor[dst[e]], 1);
        g_src_sorted[pos] = src[e];
    }
}

// ---------------------------------------------------------------------------
// fused per-node kernel: one warp per dst node
// ---------------------------------------------------------------------------
__global__ __launch_bounds__(256) void node_kernel(
    const float* __restrict__ attn,
    const float* __restrict__ out_bias,
    const float* __restrict__ ln_w,
    const float* __restrict__ ln_b,
    float* __restrict__ out)
{
    const int gwarp = (blockIdx.x * blockDim.x + threadIdx.x) >> 5;
    const int lane  = threadIdx.x & 31;
    if (gwarp >= N_NODES) return;
    const int v = gwarp;
    const int f = lane * 4;

    const float4 at  = *(const float4*)(attn + f);
    const float4 fdv = *(const float4*)(g_fd + (size_t)v * F_DIM + f);

    const int beg = g_rowptr[v];
    const int end = g_rowptr[v + 1];

    float4 acc = make_float4(0.f, 0.f, 0.f, 0.f);
    float  m = -INFINITY, denom = 0.f;

    int u = (beg < end) ? g_src_sorted[beg] : 0;
    for (int p = beg; p < end; p++) {
        int unext = (p + 1 < end) ? g_src_sorted[p + 1] : 0;
        float4 fsv = *(const float4*)(g_fs + (size_t)u * F_DIM + f);
        float sx = fsv.x + fdv.x, sy = fsv.y + fdv.y;
        float sz = fsv.z + fdv.z, sw = fsv.w + fdv.w;
        sx = (sx > 0.f) ? sx : NEG_SLOPE * sx;
        sy = (sy > 0.f) ? sy : NEG_SLOPE * sy;
        sz = (sz > 0.f) ? sz : NEG_SLOPE * sz;
        sw = (sw > 0.f) ? sw : NEG_SLOPE * sw;
        float part = sx * at.x + sy * at.y + sz * at.z + sw * at.w;
        part += __shfl_xor_sync(0xffffffffu, part, 1);
        part += __shfl_xor_sync(0xffffffffu, part, 2);
        part += __shfl_xor_sync(0xffffffffu, part, 4);
        float logit = part;

        float mn = fmaxf(m, logit);
        float c  = __expf(m - mn);
        float w  = __expf(logit - mn);
        denom = denom * c + w;
        acc.x = acc.x * c + w * fsv.x;
        acc.y = acc.y * c + w * fsv.y;
        acc.z = acc.z * c + w * fsv.z;
        acc.w = acc.w * c + w * fsv.w;
        m = mn;
        u = unext;
    }

    float inv = (end > beg) ? (1.f / denom) : 0.f;
    float4 ob = *(const float4*)(out_bias + f);
    float4 h;
    h.x = acc.x * inv + ob.x;
    h.y = acc.y * inv + ob.y;
    h.z = acc.z * inv + ob.z;
    h.w = acc.w * inv + ob.w;

    float s1 = h.x + h.y + h.z + h.w;
#pragma unroll
    for (int d = 16; d >= 1; d >>= 1) s1 += __shfl_xor_sync(0xffffffffu, s1, d);
    float mean = s1 * (1.f / 128.f);

    float dx = h.x - mean, dy = h.y - mean, dz = h.z - mean, dw = h.w - mean;
    float s2 = dx * dx + dy * dy + dz * dz + dw * dw;
#pragma unroll
    for (int d = 16; d >= 1; d >>= 1) s2 += __shfl_xor_sync(0xffffffffu, s2, d);
    float rstd = rsqrtf(s2 * (1.f / 128.f) + LN_EPS);

    float4 w4 = *(const float4*)(ln_w + f);
    float4 b4 = *(const float4*)(ln_b + f);
    float4 o;
    o.x = dx * rstd * w4.x + b4.x;
    o.y = dy * rstd * w4.y + b4.y;
    o.z = dz * rstd * w4.z + b4.z;
    o.w = dw * rstd * w4.w + b4.w;
    o.x = (o.x > 0.f) ? o.x : expm1f(o.x);
    o.y = (o.y > 0.f) ? o.y : expm1f(o.y);
    o.z = (o.z > 0.f) ? o.z : expm1f(o.z);
    o.w = (o.w > 0.f) ? o.w : expm1f(o.w);

    *(float4*)(out + (size_t)v * F_DIM + f) = o;
}

// ---------------------------------------------------------------------------
// launch
// ---------------------------------------------------------------------------
extern "C" void kernel_launch(void* const* d_in, const int* in_sizes, int n_in,
                              void* d_out, int out_size)
{
    const float* x        = (const float*)d_in[0];
    const float* W_src    = (const float*)d_in[1];
    const float* b_src    = (const float*)d_in[2];
    const float* W_dst    = (const float*)d_in[3];
    const float* b_dst    = (const float*)d_in[4];
    const float* attn     = (const float*)d_in[5];
    const float* out_bias = (const float*)d_in[6];
    const float* ln_w     = (const float*)d_in[7];
    const float* ln_b     = (const float*)d_in[8];
    const int*   src      = (const int*)d_in[9];
    const int*   dst      = (const int*)d_in[10];
    float* out = (float*)d_out;

    static int smem_set = 0;
    if (!smem_set) {
        cudaFuncSetAttribute(gemm_mma_kernel,
                             cudaFuncAttributeMaxDynamicSharedMemorySize, SM_TOTAL);
        smem_set = 1;
    }

    zero_kernel<<<(N_NODES + 255) / 256, 256>>>();
    convert_w_kernel<<<2, 256>>>(W_src, W_dst);

    gemm_mma_kernel<<<(N_NODES + 127) / 128, 256, SM_TOTAL>>>(x, b_src, b_dst);

    hist_kernel<<<(E_EDGES + 255) / 256, 256>>>(dst);
    scan1_kernel<<<49, 1024>>>();
    scan2_kernel<<<1, 64>>>();
    scan3_kernel<<<49, 1024>>>();
    scatter_kernel<<<(E_EDGES + 255) / 256, 256>>>(src, dst);

    int nblocks = (N_NODES * 32 + 255) / 256;
    node_kernel<<<nblocks, 256>>>(attn, out_bias, ln_w, ln_b, out);
}

// round 4
// speedup vs baseline: 1.2641x; 1.1416x over previous
#include <cuda_runtime.h>
#include <cuda_bf16.h>
#include <math.h>
#include <stdint.h>

// ---------------------------------------------------------------------------
// GATv2 layer. GEMMs via mma.sync bf16 (3-term hi/lo split, fp32 accum).
// ---------------------------------------------------------------------------

#define N_NODES 50000
#define E_EDGES 800000
#define F_DIM   128
#define NEG_SLOPE 0.2f
#define LN_EPS  1e-12f
#define NTILES  ((N_NODES + 127) / 128)   // 391

// ---- device scratch ----
__device__ float g_fs[(size_t)N_NODES * F_DIM];
__device__ float g_fd[(size_t)N_NODES * F_DIM];
__device__ int   g_deg[N_NODES];
__device__ int   g_rowptr[N_NODES + 1];
__device__ int   g_cursor[N_NODES];
__device__ int   g_src_sorted[E_EDGES];
__device__ int   g_blocksums[64];
__device__ int   g_blockoff[64];
// W^T hi/lo bf16 images, row-major [n][k]  ([2] = src/dst)
__device__ __nv_bfloat16 g_wt_hi[2][128 * 128];
__device__ __nv_bfloat16 g_wt_lo[2][128 * 128];

__device__ __forceinline__ uint32_t smem_u32(const void* p) {
    uint32_t a;
    asm("{ .reg .u64 t; cvta.to.shared.u64 t, %1; cvt.u32.u64 %0, t; }"
        : "=r"(a) : "l"(p));
    return a;
}
__device__ __forceinline__ uint32_t pack2(float a, float b) {
    __nv_bfloat162 t = __floats2bfloat162_rn(a, b);
    return *reinterpret_cast<uint32_t*>(&t);
}
__device__ __forceinline__ void ldsm_x4(uint32_t* r, uint32_t addr) {
    asm volatile("ldmatrix.sync.aligned.m8n8.x4.shared.b16 {%0,%1,%2,%3}, [%4];"
                 : "=r"(r[0]), "=r"(r[1]), "=r"(r[2]), "=r"(r[3]) : "r"(addr));
}
__device__ __forceinline__ void mma_bf16(float* d, const uint32_t* a,
                                         uint32_t b0, uint32_t b1) {
    asm volatile(
        "mma.sync.aligned.m16n8k16.row.col.f32.bf16.bf16.f32 "
        "{%0,%1,%2,%3}, {%4,%5,%6,%7}, {%8,%9}, {%0,%1,%2,%3};"
        : "+f"(d[0]), "+f"(d[1]), "+f"(d[2]), "+f"(d[3])
        : "r"(a[0]), "r"(a[1]), "r"(a[2]), "r"(a[3]), "r"(b0), "r"(b1));
}

// ---------------------------------------------------------------------------
// W transpose + hi/lo split:  g_wt[n][k] = split(W[k][n])
// ---------------------------------------------------------------------------
__global__ void convert_w_kernel(const float* __restrict__ Wsrc,
                                 const float* __restrict__ Wdst) {
    const int b = blockIdx.x;
    const float* W = b == 0 ? Wsrc : Wdst;
    for (int idx = threadIdx.x; idx < 128 * 128; idx += blockDim.x) {
        int k = idx >> 7, n = idx & 127;
        float v = W[idx];
        __nv_bfloat16 hi = __float2bfloat16(v);
        float r = v - __bfloat162float(hi);
        g_wt_hi[b][n * 128 + k] = hi;
        g_wt_lo[b][n * 128 + k] = __float2bfloat16(r);
    }
}

// ---------------------------------------------------------------------------
// Persistent GEMM: 148 CTAs, each loops over tiles; B images loaded once.
// smem (bf16, padded stride 136): A_hi, A_lo, B[2][hi/lo]
// warps 4x2: warp = 32 rows x 64 cols; mma m16n8k16; 3 terms.
// ---------------------------------------------------------------------------
#define PAD 136
#define TILE_B (128 * PAD)
#define SM_TOTAL (6 * TILE_B * 2)     // 208896 bytes

__global__ __launch_bounds__(256, 1) void gemm_mma_kernel(
    const float* __restrict__ x,
    const float* __restrict__ bsrc, const float* __restrict__ bdst)
{
    extern __shared__ __nv_bfloat16 sm[];
    __nv_bfloat16* As_hi = sm;
    __nv_bfloat16* As_lo = sm + TILE_B;
    __nv_bfloat16* Bs[2][2];
    Bs[0][0] = sm + 2 * TILE_B;
    Bs[0][1] = sm + 3 * TILE_B;
    Bs[1][0] = sm + 4 * TILE_B;
    Bs[1][1] = sm + 5 * TILE_B;

    const int tid = threadIdx.x, wid = tid >> 5, lane = tid & 31;
    const int wm = wid >> 1, wn = wid & 1;

    // ---- fill B images once ----
    for (int i = tid; i < 2048; i += 256) {
        int n = i >> 4, k = (i & 15) << 3;
        *(float4*)(Bs[0][0] + n * PAD + k) = *(const float4*)(g_wt_hi[0] + n * 128 + k);
        *(float4*)(Bs[0][1] + n * PAD + k) = *(const float4*)(g_wt_lo[0] + n * 128 + k);
        *(float4*)(Bs[1][0] + n * PAD + k) = *(const float4*)(g_wt_hi[1] + n * 128 + k);
        *(float4*)(Bs[1][1] + n * PAD + k) = *(const float4*)(g_wt_lo[1] + n * 128 + k);
    }

    const uint32_t sbase = smem_u32(sm);
    const int g = lane >> 3, l7 = lane & 7;

    for (int tile = blockIdx.x; tile < NTILES; tile += gridDim.x) {
        const int row0 = tile * 128;
        __syncthreads();   // previous compute done (and B ready on iter 0)

        // ---- load x tile, split hi/lo ----
        for (int i = tid; i < 4096; i += 256) {
            int r = i >> 5, c = (i & 31) << 2;
            float4 v = make_float4(0.f, 0.f, 0.f, 0.f);
            if (row0 + r < N_NODES)
                v = *(const float4*)(x + (size_t)(row0 + r) * F_DIM + c);
            __nv_bfloat162 h01 = __floats2bfloat162_rn(v.x, v.y);
            __nv_bfloat162 h23 = __floats2bfloat162_rn(v.z, v.w);
            uint32_t lo01 = pack2(v.x - __bfloat162float(h01.x), v.y - __bfloat162float(h01.y));
            uint32_t lo23 = pack2(v.z - __bfloat162float(h23.x), v.w - __bfloat162float(h23.y));
            uint32_t* ph = (uint32_t*)(As_hi + r * PAD + c);
            uint32_t* pl = (uint32_t*)(As_lo + r * PAD + c);
            ph[0] = *reinterpret_cast<uint32_t*>(&h01);
            ph[1] = *reinterpret_cast<uint32_t*>(&h23);
            pl[0] = lo01;
            pl[1] = lo23;
        }
        __syncthreads();

        for (int wsel = 0; wsel < 2; wsel++) {
            float acc[2][8][4];
#pragma unroll
            for (int i = 0; i < 2; i++)
#pragma unroll
                for (int j = 0; j < 8; j++)
#pragma unroll
                    for (int q = 0; q < 4; q++) acc[i][j][q] = 0.f;

#pragma unroll
            for (int term = 0; term < 3; term++) {
                const __nv_bfloat16* Asm = (term == 2) ? As_lo : As_hi;
                const __nv_bfloat16* Bsm = Bs[wsel][(term == 1) ? 1 : 0];
                const uint32_t abase = sbase + (uint32_t)((Asm - sm) * 2);
                const uint32_t bbase = sbase + (uint32_t)((Bsm - sm) * 2);
#pragma unroll
                for (int k0 = 0; k0 < 128; k0 += 16) {
                    uint32_t afr[2][4];
#pragma unroll
                    for (int mt = 0; mt < 2; mt++) {
                        int r = wm * 32 + mt * 16 + ((g & 1) << 3) + l7;
                        int c = k0 + ((g >> 1) << 3);
                        ldsm_x4(afr[mt], abase + (uint32_t)(r * PAD + c) * 2);
                    }
#pragma unroll
                    for (int p = 0; p < 4; p++) {
                        int r = wn * 64 + p * 16 + ((g >> 1) << 3) + l7;
                        int c = k0 + ((g & 1) << 3);
                        uint32_t bfr[4];
                        ldsm_x4(bfr, bbase + (uint32_t)(r * PAD + c) * 2);
#pragma unroll
                        for (int mt = 0; mt < 2; mt++) {
                            mma_bf16(acc[mt][2 * p],     afr[mt], bfr[0], bfr[1]);
                            mma_bf16(acc[mt][2 * p + 1], afr[mt], bfr[2], bfr[3]);
                        }
                    }
                }
            }

            // ---- epilogue: bias + store ----
            const float* bias = wsel ? bdst : bsrc;
            float* outp = wsel ? g_fd : g_fs;
#pragma unroll
            for (int mt = 0; mt < 2; mt++) {
#pragma unroll
                for (int nt = 0; nt < 8; nt++) {
                    int col = wn * 64 + nt * 8 + (lane & 3) * 2;
                    float bx = bias[col], by = bias[col + 1];
                    int r0 = row0 + wm * 32 + mt * 16 + (lane >> 2);
                    if (r0 < N_NODES) {
                        float2 o = make_float2(acc[mt][nt][0] + bx, acc[mt][nt][1] + by);
                        *(float2*)(outp + (size_t)r0 * F_DIM + col) = o;
                    }
                    int r1 = r0 + 8;
                    if (r1 < N_NODES) {
                        float2 o = make_float2(acc[mt][nt][2] + bx, acc[mt][nt][3] + by);
                        *(float2*)(outp + (size_t)r1 * F_DIM + col) = o;
                    }
                }
            }
        }
    }
}

// ---------------------------------------------------------------------------
// histogram / hierarchical scan / scatter  (4 edges per thread, int4 loads)
// ---------------------------------------------------------------------------
__global__ void zero_kernel() {
    int i = blockIdx.x * blockDim.x + threadIdx.x;
    if (i < N_NODES) g_deg[i] = 0;
}

__global__ void hist_kernel(const int* __restrict__ dst) {
    int e4 = blockIdx.x * blockDim.x + threadIdx.x;
    if (e4 < E_EDGES / 4) {
        int4 d = ((const int4*)dst)[e4];
        atomicAdd(&g_deg[d.x], 1);
        atomicAdd(&g_deg[d.y], 1);
        atomicAdd(&g_deg[d.z], 1);
        atomicAdd(&g_deg[d.w], 1);
    }
}

__global__ __launch_bounds__(1024) void scan1_kernel() {
    __shared__ int ws[32];
    const int tid = threadIdx.x, lane = tid & 31, wid = tid >> 5;
    int i = blockIdx.x * 1024 + tid;
    int v = (i < N_NODES) ? g_deg[i] : 0;
    int xv = v;
#pragma unroll
    for (int d = 1; d < 32; d <<= 1) {
        int t = __shfl_up_sync(0xffffffffu, xv, d);
        if (lane >= d) xv += t;
    }
    if (lane == 31) ws[wid] = xv;
    __syncthreads();
    if (wid == 0) {
        int y = ws[lane];
#pragma unroll
        for (int d = 1; d < 32; d <<= 1) {
            int t = __shfl_up_sync(0xffffffffu, y, d);
            if (lane >= d) y += t;
        }
        ws[lane] = y;
    }
    __syncthreads();
    int off = (wid > 0) ? ws[wid - 1] : 0;
    int incl = xv + off;
    if (i < N_NODES) g_rowptr[i] = incl - v;
    if (tid == 1023) g_blocksums[blockIdx.x] = incl;
}

__global__ void scan2_kernel() {
    __shared__ int s[64];
    int t = threadIdx.x;
    int v = (t < 49) ? g_blocksums[t] : 0;
    s[t] = v;
    __syncthreads();
    for (int d = 1; d < 64; d <<= 1) {
        int add = (t >= d) ? s[t - d] : 0;
        __syncthreads();
        s[t] += add;
        __syncthreads();
    }
    g_blockoff[t] = s[t] - v;
}

__global__ __launch_bounds__(1024) void scan3_kernel() {
    int i = blockIdx.x * 1024 + threadIdx.x;
    if (i < N_NODES) {
        int val = g_rowptr[i] + g_blockoff[blockIdx.x];
        g_rowptr[i] = val;
        g_cursor[i] = val;
    }
    if (i == 0) g_rowptr[N_NODES] = E_EDGES;
}

__global__ void scatter_kernel(const int* __restrict__ src, const int* __restrict__ dst) {
    int e4 = blockIdx.x * blockDim.x + threadIdx.x;
    if (e4 < E_EDGES / 4) {
        int4 s = ((const int4*)src)[e4];
        int4 d = ((const int4*)dst)[e4];
        int p0 = atomicAdd(&g_cursor[d.x], 1); g_src_sorted[p0] = s.x;
        int p1 = atomicAdd(&g_cursor[d.y], 1); g_src_sorted[p1] = s.y;
        int p2 = atomicAdd(&g_cursor[d.z], 1); g_src_sorted[p2] = s.z;
        int p3 = atomicAdd(&g_cursor[d.w], 1); g_src_sorted[p3] = s.w;
    }
}

// ---------------------------------------------------------------------------
// fused per-node kernel: one warp per dst node, paired-edge online softmax
// ---------------------------------------------------------------------------
__device__ __forceinline__ float edge_logit(const float4 fsv, const float4 fdv,
                                            const float4 at) {
    float sx = fsv.x + fdv.x, sy = fsv.y + fdv.y;
    float sz = fsv.z + fdv.z, sw = fsv.w + fdv.w;
    sx = (sx > 0.f) ? sx : NEG_SLOPE * sx;
    sy = (sy > 0.f) ? sy : NEG_SLOPE * sy;
    sz = (sz > 0.f) ? sz : NEG_SLOPE * sz;
    sw = (sw > 0.f) ? sw : NEG_SLOPE * sw;
    float part = sx * at.x + sy * at.y + sz * at.z + sw * at.w;
    part += __shfl_xor_sync(0xffffffffu, part, 1);
    part += __shfl_xor_sync(0xffffffffu, part, 2);
    part += __shfl_xor_sync(0xffffffffu, part, 4);
    return part;
}

__global__ __launch_bounds__(256) void node_kernel(
    const float* __restrict__ attn,
    const float* __restrict__ out_bias,
    const float* __restrict__ ln_w,
    const float* __restrict__ ln_b,
    float* __restrict__ out)
{
    const int gwarp = (blockIdx.x * blockDim.x + threadIdx.x) >> 5;
    const int lane  = threadIdx.x & 31;
    if (gwarp >= N_NODES) return;
    const int v = gwarp;
    const int f = lane * 4;

    const float4 at  = *(const float4*)(attn + f);
    const float4 fdv = *(const float4*)(g_fd + (size_t)v * F_DIM + f);

    const int beg = g_rowptr[v];
    const int end = g_rowptr[v + 1];

    float4 acc = make_float4(0.f, 0.f, 0.f, 0.f);
    float  m = -INFINITY, denom = 0.f;

    int p = beg;
    for (; p + 2 <= end; p += 2) {
        int u0 = g_src_sorted[p];
        int u1 = g_src_sorted[p + 1];
        float4 f0 = *(const float4*)(g_fs + (size_t)u0 * F_DIM + f);
        float4 f1 = *(const float4*)(g_fs + (size_t)u1 * F_DIM + f);
        float l0 = edge_logit(f0, fdv, at);
        float l1 = edge_logit(f1, fdv, at);
        float mn = fmaxf(m, fmaxf(l0, l1));
        float c  = __expf(m - mn);
        float w0 = __expf(l0 - mn);
        float w1 = __expf(l1 - mn);
        denom = denom * c + w0 + w1;
        acc.x = acc.x * c + w0 * f0.x + w1 * f1.x;
        acc.y = acc.y * c + w0 * f0.y + w1 * f1.y;
        acc.z = acc.z * c + w0 * f0.z + w1 * f1.z;
        acc.w = acc.w * c + w0 * f0.w + w1 * f1.w;
        m = mn;
    }
    if (p < end) {
        int u0 = g_src_sorted[p];
        float4 f0 = *(const float4*)(g_fs + (size_t)u0 * F_DIM + f);
        float l0 = edge_logit(f0, fdv, at);
        float mn = fmaxf(m, l0);
        float c  = __expf(m - mn);
        float w0 = __expf(l0 - mn);
        denom = denom * c + w0;
        acc.x = acc.x * c + w0 * f0.x;
        acc.y = acc.y * c + w0 * f0.y;
        acc.z = acc.z * c + w0 * f0.z;
        acc.w = acc.w * c + w0 * f0.w;
        m = mn;
    }

    float inv = (end > beg) ? (1.f / denom) : 0.f;
    float4 ob = *(const float4*)(out_bias + f);
    float4 h;
    h.x = acc.x * inv + ob.x;
    h.y = acc.y * inv + ob.y;
    h.z = acc.z * inv + ob.z;
    h.w = acc.w * inv + ob.w;

    float s1 = h.x + h.y + h.z + h.w;
#pragma unroll
    for (int d = 16; d >= 1; d >>= 1) s1 += __shfl_xor_sync(0xffffffffu, s1, d);
    float mean = s1 * (1.f / 128.f);

    float dx = h.x - mean, dy = h.y - mean, dz = h.z - mean, dw = h.w - mean;
    float s2 = dx * dx + dy * dy + dz * dz + dw * dw;
#pragma unroll
    for (int d = 16; d >= 1; d >>= 1) s2 += __shfl_xor_sync(0xffffffffu, s2, d);
    float rstd = rsqrtf(s2 * (1.f / 128.f) + LN_EPS);

    float4 w4 = *(const float4*)(ln_w + f);
    float4 b4 = *(const float4*)(ln_b + f);
    float4 o;
    o.x = dx * rstd * w4.x + b4.x;
    o.y = dy * rstd * w4.y + b4.y;
    o.z = dz * rstd * w4.z + b4.z;
    o.w = dw * rstd * w4.w + b4.w;
    o.x = (o.x > 0.f) ? o.x : expm1f(o.x);
    o.y = (o.y > 0.f) ? o.y : expm1f(o.y);
    o.z = (o.z > 0.f) ? o.z : expm1f(o.z);
    o.w = (o.w > 0.f) ? o.w : expm1f(o.w);

    *(float4*)(out + (size_t)v * F_DIM + f) = o;
}

// ---------------------------------------------------------------------------
// launch  (gemm at launch index 3 -> gets profiled by the fixed ncu window)
// ---------------------------------------------------------------------------
extern "C" void kernel_launch(void* const* d_in, const int* in_sizes, int n_in,
                              void* d_out, int out_size)
{
    const float* x        = (const float*)d_in[0];
    const float* W_src    = (const float*)d_in[1];
    const float* b_src    = (const float*)d_in[2];
    const float* W_dst    = (const float*)d_in[3];
    const float* b_dst    = (const float*)d_in[4];
    const float* attn     = (const float*)d_in[5];
    const float* out_bias = (const float*)d_in[6];
    const float* ln_w     = (const float*)d_in[7];
    const float* ln_b     = (const float*)d_in[8];
    const int*   src      = (const int*)d_in[9];
    const int*   dst      = (const int*)d_in[10];
    float* out = (float*)d_out;

    static int smem_set = 0;
    if (!smem_set) {
        cudaFuncSetAttribute(gemm_mma_kernel,
                             cudaFuncAttributeMaxDynamicSharedMemorySize, SM_TOTAL);
        smem_set = 1;
    }

    zero_kernel<<<(N_NODES + 255) / 256, 256>>>();                 // 0
    convert_w_kernel<<<2, 256>>>(W_src, W_dst);                    // 1
    hist_kernel<<<(E_EDGES / 4 + 255) / 256, 256>>>(dst);          // 2
    gemm_mma_kernel<<<148, 256, SM_TOTAL>>>(x, b_src, b_dst);      // 3 (profiled)
    scan1_kernel<<<49, 1024>>>();                                  // 4
    scan2_kernel<<<1, 64>>>();                                     // 5
    scan3_kernel<<<49, 1024>>>();                                  // 6
    scatter_kernel<<<(E_EDGES / 4 + 255) / 256, 256>>>(src, dst);  // 7
    node_kernel<<<(N_NODES * 32 + 255) / 256, 256>>>(attn, out_bias, ln_w, ln_b, out); // 8
}